// round 2
// baseline (speedup 1.0000x reference)
#include <cuda_runtime.h>
#include <math_constants.h>

static constexpr int B  = 4;
static constexpr int S  = 2048;
static constexpr int D  = 512;
static constexpr int H  = 8;
static constexpr int DK = 64;
static constexpr int BH = B * H;            // 32
static constexpr float SCALE = 0.125f;      // DK^-0.5

// ---- scratch (device globals; no runtime allocation allowed) ----
__device__ float g_Q[B * H * S * DK];       // 16 MB  [b][h][s][dk]
__device__ float g_K[B * H * S * DK];       // 16 MB
__device__ float g_V[B * H * S * DK];       // 16 MB
__device__ float g_Ctx[B * S * D];          // 16 MB  [b][s][h*64+dk]
__device__ float g_Sc[BH * S * S];          // 512 MB scores -> probs (in place)
__device__ float g_M[BH * S];               // row max
__device__ float g_Li[BH * S];              // 1 / row sum

// ============================================================
// QKV projection: [8192 x 512] @ [512 x 1536], scattered into
// g_Q/g_K/g_V with [b][h][s][dk] layout.
// ============================================================
__global__ __launch_bounds__(256) void qkv_proj_kernel(
    const float* __restrict__ Zq, const float* __restrict__ Zkv,
    const float* __restrict__ W)
{
    const int m0   = blockIdx.x * 64;
    const int n0   = blockIdx.y * 64;          // 0..1535
    const int part = n0 >> 9;                  // 0=Q 1=K 2=V
    const float* A = (part == 0) ? Zq : Zkv;
    float* dst = (part == 0) ? g_Q : (part == 1) ? g_K : g_V;
    const int dcol0 = n0 - (part << 9);

    __shared__ float AsT[16][68];   // [k][m], +4 pad keeps 16B alignment
    __shared__ float Bs[16][68];    // [k][n]

    const int t  = threadIdx.x;
    const int tx = t & 15, ty = t >> 4;
    const int ar = t >> 2,  ac = (t & 3) << 2;
    const int br = t >> 4,  bc = (t & 15) << 2;

    float acc[4][4] = {};

    for (int kt = 0; kt < 512; kt += 16) {
        float4 av = *(const float4*)(A + (size_t)(m0 + ar) * 512 + kt + ac);
        AsT[ac + 0][ar] = av.x;
        AsT[ac + 1][ar] = av.y;
        AsT[ac + 2][ar] = av.z;
        AsT[ac + 3][ar] = av.w;
        *(float4*)&Bs[br][bc] =
            *(const float4*)(W + (size_t)(kt + br) * 1536 + n0 + bc);
        __syncthreads();
        #pragma unroll
        for (int kk = 0; kk < 16; kk++) {
            float4 a4 = *(float4*)&AsT[kk][ty << 2];
            float4 b4 = *(float4*)&Bs[kk][tx << 2];
            float a[4] = {a4.x, a4.y, a4.z, a4.w};
            float b[4] = {b4.x, b4.y, b4.z, b4.w};
            #pragma unroll
            for (int i = 0; i < 4; i++)
                #pragma unroll
                for (int j = 0; j < 4; j++)
                    acc[i][j] += a[i] * b[j];
        }
        __syncthreads();
    }

    #pragma unroll
    for (int i = 0; i < 4; i++) {
        const int m  = m0 + (ty << 2) + i;
        const int bb = m >> 11, ss = m & 2047;
        #pragma unroll
        for (int j = 0; j < 4; j++) {
            const int d  = dcol0 + (tx << 2) + j;
            const int hh = d >> 6, dk = d & 63;
            dst[(((size_t)bb * H + hh) * S + ss) * DK + dk] = acc[i][j];
        }
    }
}

// ============================================================
// scores = Q @ K^T * scale + mask   (per b,h; K=64 in one tile)
// ============================================================
__global__ __launch_bounds__(256) void scores_kernel(const float* __restrict__ mask)
{
    const int bh = blockIdx.z;
    const int q0 = blockIdx.x * 64;
    const int k0 = blockIdx.y * 64;
    const float* Qp = g_Q + (size_t)bh * S * DK;
    const float* Kp = g_K + (size_t)bh * S * DK;

    __shared__ float QsT[64][68];   // [dk][q]
    __shared__ float KsT[64][68];   // [dk][k]

    const int t = threadIdx.x, tx = t & 15, ty = t >> 4;

    #pragma unroll
    for (int it = 0; it < 4; it++) {
        const int f4 = it * 256 + t;
        const int r = f4 >> 4, c = (f4 & 15) << 2;
        float4 qv = *(const float4*)(Qp + (size_t)(q0 + r) * DK + c);
        QsT[c + 0][r] = qv.x; QsT[c + 1][r] = qv.y;
        QsT[c + 2][r] = qv.z; QsT[c + 3][r] = qv.w;
        float4 kv = *(const float4*)(Kp + (size_t)(k0 + r) * DK + c);
        KsT[c + 0][r] = kv.x; KsT[c + 1][r] = kv.y;
        KsT[c + 2][r] = kv.z; KsT[c + 3][r] = kv.w;
    }
    __syncthreads();

    float acc[4][4] = {};
    #pragma unroll
    for (int kk = 0; kk < 64; kk++) {
        float4 a4 = *(float4*)&QsT[kk][ty << 2];
        float4 b4 = *(float4*)&KsT[kk][tx << 2];
        float a[4] = {a4.x, a4.y, a4.z, a4.w};
        float b[4] = {b4.x, b4.y, b4.z, b4.w};
        #pragma unroll
        for (int i = 0; i < 4; i++)
            #pragma unroll
            for (int j = 0; j < 4; j++)
                acc[i][j] += a[i] * b[j];
    }

    float* Sp = g_Sc + (size_t)bh * S * S;
    #pragma unroll
    for (int i = 0; i < 4; i++) {
        const int q = q0 + (ty << 2) + i;
        #pragma unroll
        for (int j = 0; j < 4; j++) {
            const int kc = k0 + (tx << 2) + j;
            Sp[(size_t)q * S + kc] = acc[i][j] * SCALE + mask[(size_t)q * S + kc];
        }
    }
}

// ============================================================
// Per-row softmax stats: m = max, Li = 1/sum(exp(s-m))
// One block (256 thr) per row; row (2048 fl) held in registers.
// ============================================================
__global__ __launch_bounds__(256) void rowstat_kernel()
{
    const int row = blockIdx.x;                 // 0 .. BH*S-1
    const float* p = g_Sc + (size_t)row * S;
    const int t = threadIdx.x;

    float v[8];
    float m = -CUDART_INF_F;
    #pragma unroll
    for (int j = 0; j < 8; j++) { v[j] = p[t + 256 * j]; m = fmaxf(m, v[j]); }

    __shared__ float red[32];
    #pragma unroll
    for (int o = 16; o > 0; o >>= 1)
        m = fmaxf(m, __shfl_xor_sync(0xffffffffu, m, o));
    if ((t & 31) == 0) red[t >> 5] = m;
    __syncthreads();
    if (t < 32) {
        float x = (t < 8) ? red[t] : -CUDART_INF_F;
        #pragma unroll
        for (int o = 4; o > 0; o >>= 1)
            x = fmaxf(x, __shfl_xor_sync(0xffffffffu, x, o));
        if (t == 0) red[0] = x;
    }
    __syncthreads();
    m = red[0];
    __syncthreads();

    float l = 0.f;
    #pragma unroll
    for (int j = 0; j < 8; j++) l += __expf(v[j] - m);
    #pragma unroll
    for (int o = 16; o > 0; o >>= 1)
        l += __shfl_xor_sync(0xffffffffu, l, o);
    if ((t & 31) == 0) red[t >> 5] = l;
    __syncthreads();
    if (t == 0) {
        float sum = 0.f;
        #pragma unroll
        for (int w = 0; w < 8; w++) sum += red[w];
        g_M[row]  = m;
        g_Li[row] = 1.0f / sum;
    }
}

// ============================================================
// ctx = softmax(S) @ V, N=DK=64 in one tile; probs are computed
// on load (read-once) and stored back into g_Sc for the mean pass.
// ============================================================
__global__ __launch_bounds__(256) void ctx_kernel()
{
    const int bh = blockIdx.y;
    const int q0 = blockIdx.x * 64;
    const int b = bh >> 3, h = bh & 7;

    __shared__ float PsT[64][68];   // [k][q]
    __shared__ float Vs[64][68];    // [k][dk]
    __shared__ float sm_m[64], sm_li[64];

    const int t = threadIdx.x, tx = t & 15, ty = t >> 4;
    if (t < 64) {
        const int row = bh * S + q0 + t;
        sm_m[t]  = g_M[row];
        sm_li[t] = g_Li[row];
    }
    __syncthreads();

    float* Sp = g_Sc + (size_t)bh * S * S;
    const float* Vp = g_V + (size_t)bh * S * DK;

    float acc[4][4] = {};

    for (int kt = 0; kt < S; kt += 64) {
        #pragma unroll
        for (int it = 0; it < 4; it++) {
            const int f4 = it * 256 + t;
            const int r = f4 >> 4, c = (f4 & 15) << 2;
            float* sp = Sp + (size_t)(q0 + r) * S + kt + c;
            float4 sv = *(const float4*)sp;
            const float mm = sm_m[r], li = sm_li[r];
            float4 pv;
            pv.x = __expf(sv.x - mm) * li;
            pv.y = __expf(sv.y - mm) * li;
            pv.z = __expf(sv.z - mm) * li;
            pv.w = __expf(sv.w - mm) * li;
            PsT[c + 0][r] = pv.x; PsT[c + 1][r] = pv.y;
            PsT[c + 2][r] = pv.z; PsT[c + 3][r] = pv.w;
            *(float4*)sp = pv;                         // probs for mean pass
            *(float4*)&Vs[r][c] =
                *(const float4*)(Vp + (size_t)(kt + r) * DK + c);
        }
        __syncthreads();
        #pragma unroll
        for (int kk = 0; kk < 64; kk++) {
            float4 a4 = *(float4*)&PsT[kk][ty << 2];
            float4 b4 = *(float4*)&Vs[kk][tx << 2];
            float a[4] = {a4.x, a4.y, a4.z, a4.w};
            float bb[4] = {b4.x, b4.y, b4.z, b4.w};
            #pragma unroll
            for (int i = 0; i < 4; i++)
                #pragma unroll
                for (int j = 0; j < 4; j++)
                    acc[i][j] += a[i] * bb[j];
        }
        __syncthreads();
    }

    #pragma unroll
    for (int i = 0; i < 4; i++) {
        const int q = q0 + (ty << 2) + i;
        #pragma unroll
        for (int j = 0; j < 4; j++)
            g_Ctx[((size_t)b * S + q) * D + h * DK + (tx << 2) + j] = acc[i][j];
    }
}

// ============================================================
// attn.mean(axis=1): mean over heads of the prob tensor.
// ============================================================
__global__ __launch_bounds__(256) void mean_kernel(float* __restrict__ mean)
{
    const size_t idx = (size_t)blockIdx.x * 256 + threadIdx.x;  // < B*S*S
    const int bb = (int)(idx / ((size_t)S * S));
    const size_t r = idx - (size_t)bb * S * S;
    float s = 0.f;
    #pragma unroll
    for (int hh = 0; hh < H; hh++)
        s += g_Sc[(size_t)(bb * H + hh) * S * S + r];
    mean[idx] = s * 0.125f;
}

// ============================================================
// out = Ctx @ Wout : [8192 x 512] @ [512 x 512]
// ============================================================
__global__ __launch_bounds__(256) void out_proj_kernel(
    const float* __restrict__ W, float* __restrict__ out)
{
    const int m0 = blockIdx.x * 64;
    const int n0 = blockIdx.y * 64;

    __shared__ float AsT[16][68];
    __shared__ float Bs[16][68];

    const int t  = threadIdx.x;
    const int tx = t & 15, ty = t >> 4;
    const int ar = t >> 2,  ac = (t & 3) << 2;
    const int br = t >> 4,  bc = (t & 15) << 2;

    float acc[4][4] = {};

    for (int kt = 0; kt < 512; kt += 16) {
        float4 av = *(const float4*)(g_Ctx + (size_t)(m0 + ar) * 512 + kt + ac);
        AsT[ac + 0][ar] = av.x;
        AsT[ac + 1][ar] = av.y;
        AsT[ac + 2][ar] = av.z;
        AsT[ac + 3][ar] = av.w;
        *(float4*)&Bs[br][bc] =
            *(const float4*)(W + (size_t)(kt + br) * 512 + n0 + bc);
        __syncthreads();
        #pragma unroll
        for (int kk = 0; kk < 16; kk++) {
            float4 a4 = *(float4*)&AsT[kk][ty << 2];
            float4 b4 = *(float4*)&Bs[kk][tx << 2];
            float a[4] = {a4.x, a4.y, a4.z, a4.w};
            float b[4] = {b4.x, b4.y, b4.z, b4.w};
            #pragma unroll
            for (int i = 0; i < 4; i++)
                #pragma unroll
                for (int j = 0; j < 4; j++)
                    acc[i][j] += a[i] * b[j];
        }
        __syncthreads();
    }

    #pragma unroll
    for (int i = 0; i < 4; i++)
        #pragma unroll
        for (int j = 0; j < 4; j++)
            out[(size_t)(m0 + (ty << 2) + i) * 512 + n0 + (tx << 2) + j] = acc[i][j];
}

// ============================================================
extern "C" void kernel_launch(void* const* d_in, const int* in_sizes, int n_in,
                              void* d_out, int out_size)
{
    const float* Zq   = (const float*)d_in[0];
    const float* Zkv  = (const float*)d_in[1];
    const float* mask = (const float*)d_in[2];
    const float* Wqkv = (const float*)d_in[3];
    const float* Wout = (const float*)d_in[4];

    float* out  = (float*)d_out;                 // [B,S,D]
    float* mean = out + (size_t)B * S * D;       // [B,S,S]

    qkv_proj_kernel<<<dim3(128, 24), 256>>>(Zq, Zkv, Wqkv);
    scores_kernel<<<dim3(32, 32, 32), 256>>>(mask);
    rowstat_kernel<<<BH * S, 256>>>();
    ctx_kernel<<<dim3(32, 32), 256>>>();
    mean_kernel<<<(B * S * S) / 256, 256>>>(mean);
    out_proj_kernel<<<dim3(128, 8), 256>>>(Wout, out);
}

// round 5
// speedup vs baseline: 1.6773x; 1.6773x over previous
#include <cuda_runtime.h>
#include <math_constants.h>

static constexpr int B  = 4;
static constexpr int S  = 2048;
static constexpr int D  = 512;
static constexpr int H  = 8;
static constexpr int DK = 64;
static constexpr int BH = B * H;            // 32
static constexpr float SCALE = 0.125f;      // DK^-0.5

// ---- scratch (device globals; no runtime allocation allowed) ----
__device__ float g_Q[B * H * S * DK];       // 16 MB  [bh][s][dk]
__device__ float g_K[B * H * S * DK];       // 16 MB  [bh][s][dk]
__device__ float g_Vt[B * H * DK * S];      // 16 MB  [bh][dk][s]  (transposed!)
__device__ float g_Ctx[B * S * D];          // 16 MB  [b][s][h*64+dk]
__device__ float g_Sc[(size_t)BH * S * S];  // 512 MB scores -> probs (in place)
__device__ float g_M[BH * S];               // row max
__device__ float g_Li[BH * S];              // 1 / row sum

// packed f32x2 FMA: d.lo += a.lo*b.lo ; d.hi += a.hi*b.hi
__device__ __forceinline__ void ffma2(unsigned long long& d,
                                      unsigned long long a,
                                      unsigned long long b) {
    asm("fma.rn.f32x2 %0, %1, %2, %0;" : "+l"(d) : "l"(a), "l"(b));
}
__device__ __forceinline__ float pairsum(unsigned long long v) {
    return __uint_as_float((unsigned)v) + __uint_as_float((unsigned)(v >> 32));
}

// ============================================================
// QKV projection: [8192 x 512] @ [512 x 1536] -> g_Q, g_K, g_Vt
// 64x64 tile, k-chunk 64, 4x4 strided microtile, FFMA2 k-pairs.
// ============================================================
__global__ __launch_bounds__(256, 2) void qkv_proj_kernel(
    const float* __restrict__ Zq, const float* __restrict__ Zkv,
    const float* __restrict__ W)
{
    const int m0   = blockIdx.x * 64;
    const int n0   = blockIdx.y * 64;          // 0..1535
    const int part = n0 >> 9;                  // 0=Q 1=K 2=V
    const float* A = (part == 0) ? Zq : Zkv;
    const int dcol0 = n0 - (part << 9);

    __shared__ float As[64][66];   // [m][k], k contiguous
    __shared__ float Bs[64][66];   // [n][k], k contiguous

    const int t = threadIdx.x, tx = t & 15, ty = t >> 4;

    unsigned long long acc[4][4] = {};

    for (int kt = 0; kt < 512; kt += 64) {
        __syncthreads();
        // A tile 64x64 (natural layout, float2 copies)
        #pragma unroll
        for (int i = 0; i < 8; i++) {
            int idx = t + i * 256;               // float2 index 0..2047
            int r = idx >> 5, c2 = (idx & 31) << 1;
            *(float2*)&As[r][c2] =
                *(const float2*)(A + (size_t)(m0 + r) * 512 + kt + c2);
        }
        // B tile: W[kt..kt+63][n0..n0+63] transposed into Bs[n][k]
        #pragma unroll
        for (int i = 0; i < 4; i++) {
            int idx = t + i * 256;               // float4 index 0..1023
            int kr = idx >> 4, nc = (idx & 15) << 2;
            float4 w = *(const float4*)(W + (size_t)(kt + kr) * 1536 + n0 + nc);
            Bs[nc + 0][kr] = w.x; Bs[nc + 1][kr] = w.y;
            Bs[nc + 2][kr] = w.z; Bs[nc + 3][kr] = w.w;
        }
        __syncthreads();

        #pragma unroll 8
        for (int kk = 0; kk < 32; kk++) {
            unsigned long long a2[4], b2[4];
            #pragma unroll
            for (int i = 0; i < 4; i++)
                a2[i] = *(const unsigned long long*)&As[ty + 16 * i][kk << 1];
            #pragma unroll
            for (int j = 0; j < 4; j++)
                b2[j] = *(const unsigned long long*)&Bs[tx + 16 * j][kk << 1];
            #pragma unroll
            for (int i = 0; i < 4; i++)
                #pragma unroll
                for (int j = 0; j < 4; j++)
                    ffma2(acc[i][j], a2[i], b2[j]);
        }
    }

    #pragma unroll
    for (int i = 0; i < 4; i++) {
        const int m  = m0 + ty + 16 * i;
        const int bb = m >> 11, ss = m & 2047;
        #pragma unroll
        for (int j = 0; j < 4; j++) {
            const int d  = dcol0 + tx + 16 * j;
            const int hh = d >> 6, dk = d & 63;
            const float v = pairsum(acc[i][j]);
            if (part == 2)
                g_Vt[(((size_t)bb * H + hh) * DK + dk) * S + ss] = v;
            else if (part == 1)
                g_K[(((size_t)bb * H + hh) * S + ss) * DK + dk] = v;
            else
                g_Q[(((size_t)bb * H + hh) * S + ss) * DK + dk] = v;
        }
    }
}

// ============================================================
// scores = Q @ K^T * scale + mask, fused online-softmax rowstats.
// Block owns a full 64-row strip across all 2048 k columns.
// ============================================================
__global__ __launch_bounds__(256, 2) void scores_kernel(const float* __restrict__ mask)
{
    const int bh = blockIdx.y;
    const int q0 = blockIdx.x * 64;
    const float* Qp = g_Q + (size_t)bh * S * DK;
    const float* Kp = g_K + (size_t)bh * S * DK;
    float* Sp = g_Sc + (size_t)bh * S * S;

    __shared__ float Qs[64][66];   // [q][dk]
    __shared__ float Ks[64][66];   // [k][dk]

    const int t = threadIdx.x, tx = t & 15, ty = t >> 4;

    // load Q tile once
    #pragma unroll
    for (int i = 0; i < 8; i++) {
        int idx = t + i * 256;
        int r = idx >> 5, c2 = (idx & 31) << 1;
        *(float2*)&Qs[r][c2] =
            *(const float2*)(Qp + (size_t)(q0 + r) * DK + c2);
    }

    float m_run[4], l_run[4];
    #pragma unroll
    for (int i = 0; i < 4; i++) { m_run[i] = -CUDART_INF_F; l_run[i] = 0.f; }

    for (int kt = 0; kt < S; kt += 64) {
        __syncthreads();
        #pragma unroll
        for (int i = 0; i < 8; i++) {
            int idx = t + i * 256;
            int r = idx >> 5, c2 = (idx & 31) << 1;
            *(float2*)&Ks[r][c2] =
                *(const float2*)(Kp + (size_t)(kt + r) * DK + c2);
        }
        __syncthreads();

        unsigned long long acc[4][4] = {};
        #pragma unroll 8
        for (int kk = 0; kk < 32; kk++) {
            unsigned long long a2[4], b2[4];
            #pragma unroll
            for (int i = 0; i < 4; i++)
                a2[i] = *(const unsigned long long*)&Qs[ty + 16 * i][kk << 1];
            #pragma unroll
            for (int j = 0; j < 4; j++)
                b2[j] = *(const unsigned long long*)&Ks[tx + 16 * j][kk << 1];
            #pragma unroll
            for (int i = 0; i < 4; i++)
                #pragma unroll
                for (int j = 0; j < 4; j++)
                    ffma2(acc[i][j], a2[i], b2[j]);
        }

        // epilogue: scale + mask, store, online softmax stats
        #pragma unroll
        for (int i = 0; i < 4; i++) {
            const int q = q0 + ty + 16 * i;
            float sv[4];
            float tmax = -CUDART_INF_F;
            #pragma unroll
            for (int j = 0; j < 4; j++) {
                const int kc = kt + tx + 16 * j;
                sv[j] = pairsum(acc[i][j]) * SCALE + mask[(size_t)q * S + kc];
                Sp[(size_t)q * S + kc] = sv[j];
                tmax = fmaxf(tmax, sv[j]);
            }
            #pragma unroll
            for (int o = 8; o > 0; o >>= 1)
                tmax = fmaxf(tmax, __shfl_xor_sync(0xffffffffu, tmax, o));
            float es = 0.f;
            #pragma unroll
            for (int j = 0; j < 4; j++) es += __expf(sv[j] - tmax);
            #pragma unroll
            for (int o = 8; o > 0; o >>= 1)
                es += __shfl_xor_sync(0xffffffffu, es, o);
            const float mn = fmaxf(m_run[i], tmax);
            l_run[i] = l_run[i] * __expf(m_run[i] - mn) + es * __expf(tmax - mn);
            m_run[i] = mn;
        }
    }

    if (tx == 0) {
        #pragma unroll
        for (int i = 0; i < 4; i++) {
            const int row = bh * S + q0 + ty + 16 * i;
            g_M[row]  = m_run[i];
            g_Li[row] = 1.0f / l_run[i];
        }
    }
}

// ============================================================
// ctx = softmax(S) @ V ; probs computed on load (read-once),
// written back in place for the mean pass. V^T layout -> no transpose.
// ============================================================
__global__ __launch_bounds__(256, 2) void ctx_kernel()
{
    const int bh = blockIdx.y;
    const int q0 = blockIdx.x * 64;
    const int b = bh >> 3, h = bh & 7;

    float* Sp = g_Sc + (size_t)bh * S * S;
    const float* Vt = g_Vt + (size_t)bh * DK * S;   // [dk][s]

    __shared__ float Ps[64][66];   // [q][k]
    __shared__ float Vs[64][66];   // [dk][k]
    __shared__ float sm_m[64], sm_li[64];

    const int t = threadIdx.x, tx = t & 15, ty = t >> 4;
    if (t < 64) {
        const int row = bh * S + q0 + t;
        sm_m[t]  = g_M[row];
        sm_li[t] = g_Li[row];
    }

    unsigned long long acc[4][4] = {};

    for (int kt = 0; kt < S; kt += 64) {
        __syncthreads();
        // scores -> probs -> smem + gmem writeback
        #pragma unroll
        for (int i = 0; i < 4; i++) {
            int idx = t + i * 256;               // float4 index
            int r = idx >> 4, c4 = (idx & 15) << 2;
            float* sp = Sp + (size_t)(q0 + r) * S + kt + c4;
            float4 sv = *(const float4*)sp;
            const float mm = sm_m[r], li = sm_li[r];
            float4 pv;
            pv.x = __expf(sv.x - mm) * li;
            pv.y = __expf(sv.y - mm) * li;
            pv.z = __expf(sv.z - mm) * li;
            pv.w = __expf(sv.w - mm) * li;
            *(float4*)sp = pv;
            float2 p0 = {pv.x, pv.y}, p1 = {pv.z, pv.w};
            *(float2*)&Ps[r][c4]     = p0;
            *(float2*)&Ps[r][c4 + 2] = p1;
        }
        // V tile (already [dk][s]) straight copy
        #pragma unroll
        for (int i = 0; i < 8; i++) {
            int idx = t + i * 256;
            int r = idx >> 5, c2 = (idx & 31) << 1;
            *(float2*)&Vs[r][c2] =
                *(const float2*)(Vt + (size_t)r * S + kt + c2);
        }
        __syncthreads();

        #pragma unroll 8
        for (int kk = 0; kk < 32; kk++) {
            unsigned long long a2[4], b2[4];
            #pragma unroll
            for (int i = 0; i < 4; i++)
                a2[i] = *(const unsigned long long*)&Ps[ty + 16 * i][kk << 1];
            #pragma unroll
            for (int j = 0; j < 4; j++)
                b2[j] = *(const unsigned long long*)&Vs[tx + 16 * j][kk << 1];
            #pragma unroll
            for (int i = 0; i < 4; i++)
                #pragma unroll
                for (int j = 0; j < 4; j++)
                    ffma2(acc[i][j], a2[i], b2[j]);
        }
    }

    #pragma unroll
    for (int i = 0; i < 4; i++) {
        const int q = q0 + ty + 16 * i;
        #pragma unroll
        for (int j = 0; j < 4; j++)
            g_Ctx[((size_t)b * S + q) * D + h * DK + tx + 16 * j] = pairsum(acc[i][j]);
    }
}

// ============================================================
// attn.mean(axis=1) over heads (vectorized float4).
// ============================================================
__global__ __launch_bounds__(256) void mean_kernel(float* __restrict__ mean)
{
    const size_t i4 = (size_t)blockIdx.x * 256 + threadIdx.x;   // < B*S*S/4
    const size_t per_b = (size_t)S * S / 4;
    const int bb = (int)(i4 / per_b);
    const size_t r4 = i4 - (size_t)bb * per_b;
    float4 sacc = {0.f, 0.f, 0.f, 0.f};
    #pragma unroll
    for (int hh = 0; hh < H; hh++) {
        const float4 v = *(const float4*)
            (g_Sc + (size_t)(bb * H + hh) * S * S + 4 * r4);
        sacc.x += v.x; sacc.y += v.y; sacc.z += v.z; sacc.w += v.w;
    }
    sacc.x *= 0.125f; sacc.y *= 0.125f; sacc.z *= 0.125f; sacc.w *= 0.125f;
    ((float4*)mean)[i4] = sacc;
}

// ============================================================
// out = Ctx @ Wout : [8192 x 512] @ [512 x 512]
// ============================================================
__global__ __launch_bounds__(256, 2) void out_proj_kernel(
    const float* __restrict__ W, float* __restrict__ out)
{
    const int m0 = blockIdx.x * 64;
    const int n0 = blockIdx.y * 64;

    __shared__ float As[64][66];
    __shared__ float Bs[64][66];

    const int t = threadIdx.x, tx = t & 15, ty = t >> 4;

    unsigned long long acc[4][4] = {};

    for (int kt = 0; kt < 512; kt += 64) {
        __syncthreads();
        #pragma unroll
        for (int i = 0; i < 8; i++) {
            int idx = t + i * 256;
            int r = idx >> 5, c2 = (idx & 31) << 1;
            *(float2*)&As[r][c2] =
                *(const float2*)(g_Ctx + (size_t)(m0 + r) * 512 + kt + c2);
        }
        #pragma unroll
        for (int i = 0; i < 4; i++) {
            int idx = t + i * 256;
            int kr = idx >> 4, nc = (idx & 15) << 2;
            float4 w = *(const float4*)(W + (size_t)(kt + kr) * 512 + n0 + nc);
            Bs[nc + 0][kr] = w.x; Bs[nc + 1][kr] = w.y;
            Bs[nc + 2][kr] = w.z; Bs[nc + 3][kr] = w.w;
        }
        __syncthreads();

        #pragma unroll 8
        for (int kk = 0; kk < 32; kk++) {
            unsigned long long a2[4], b2[4];
            #pragma unroll
            for (int i = 0; i < 4; i++)
                a2[i] = *(const unsigned long long*)&As[ty + 16 * i][kk << 1];
            #pragma unroll
            for (int j = 0; j < 4; j++)
                b2[j] = *(const unsigned long long*)&Bs[tx + 16 * j][kk << 1];
            #pragma unroll
            for (int i = 0; i < 4; i++)
                #pragma unroll
                for (int j = 0; j < 4; j++)
                    ffma2(acc[i][j], a2[i], b2[j]);
        }
    }

    #pragma unroll
    for (int i = 0; i < 4; i++)
        #pragma unroll
        for (int j = 0; j < 4; j++)
            out[(size_t)(m0 + ty + 16 * i) * 512 + n0 + tx + 16 * j] =
                pairsum(acc[i][j]);
}

// ============================================================
extern "C" void kernel_launch(void* const* d_in, const int* in_sizes, int n_in,
                              void* d_out, int out_size)
{
    const float* Zq   = (const float*)d_in[0];
    const float* Zkv  = (const float*)d_in[1];
    const float* mask = (const float*)d_in[2];
    const float* Wqkv = (const float*)d_in[3];
    const float* Wout = (const float*)d_in[4];

    float* out  = (float*)d_out;                 // [B,S,D]
    float* mean = out + (size_t)B * S * D;       // [B,S,S]

    qkv_proj_kernel<<<dim3(128, 24), 256>>>(Zq, Zkv, Wqkv);
    scores_kernel<<<dim3(32, 32), 256>>>(mask);
    ctx_kernel<<<dim3(32, 32), 256>>>();
    mean_kernel<<<(B * (size_t)S * S / 4) / 256, 256>>>(mean);
    out_proj_kernel<<<dim3(128, 8), 256>>>(Wout, out);
}

// round 8
// speedup vs baseline: 2.1905x; 1.3060x over previous
#include <cuda_runtime.h>
#include <math_constants.h>
#include <cstdint>

static constexpr int B  = 4;
static constexpr int S  = 2048;
static constexpr int D  = 512;
static constexpr int H  = 8;
static constexpr int DK = 64;
static constexpr int BH = B * H;            // 32
static constexpr float SCALE = 0.125f;      // DK^-0.5

// ---- scratch (device globals; no runtime allocation allowed) ----
__device__ float g_Q[B * H * S * DK];       // 16 MB  [bh][s][dk]
__device__ float g_K[B * H * S * DK];       // 16 MB  [bh][s][dk]
__device__ float g_V[B * H * S * DK];       // 16 MB  [bh][s][dk]
__device__ float g_Ctx[B * S * D];          // 16 MB  [b][s][h*64+dk]
__device__ float g_Sc[(size_t)BH * S * S];  // 512 MB raw masked scores
__device__ float g_M[BH * S];               // row max
__device__ float g_Li[BH * S];              // 1 / row sum

// ============================================================
// helpers
// ============================================================
__device__ __forceinline__ float tf32f(float x) {
    uint32_t u;
    asm("cvt.rna.tf32.f32 %0, %1;" : "=r"(u) : "f"(x));
    return __uint_as_float(u);
}

// m16n8k8 row.col f32.tf32.tf32.f32 warp MMA (fallback HMMA on sm_103)
__device__ __forceinline__ void mma8(float& d0, float& d1, float& d2, float& d3,
                                     uint32_t a0, uint32_t a1, uint32_t a2, uint32_t a3,
                                     uint32_t b0, uint32_t b1) {
    asm("mma.sync.aligned.m16n8k8.row.col.f32.tf32.tf32.f32 "
        "{%0,%1,%2,%3}, {%4,%5,%6,%7}, {%8,%9}, {%0,%1,%2,%3};"
        : "+f"(d0), "+f"(d1), "+f"(d2), "+f"(d3)
        : "r"(a0), "r"(a1), "r"(a2), "r"(a3), "r"(b0), "r"(b1));
}

// online softmax update with two new values
__device__ __forceinline__ void onl(float& m, float& l, float v0, float v1) {
    const float vm = fmaxf(v0, v1);
    const float mn = fmaxf(m, vm);
    l = l * __expf(m - mn) + __expf(v0 - mn) + __expf(v1 - mn);
    m = mn;
}
__device__ __forceinline__ void merge_sh(float& m, float& l, int off) {
    const float mo = __shfl_xor_sync(0xffffffffu, m, off);
    const float lo = __shfl_xor_sync(0xffffffffu, l, off);
    const float mn = fmaxf(m, mo);
    l = l * __expf(m - mn) + lo * __expf(mo - mn);
    m = mn;
}

// packed f32x2 FMA helpers (FFMA2 path for projections)
__device__ __forceinline__ void ffma2(unsigned long long& d,
                                      unsigned long long a,
                                      unsigned long long b) {
    asm("fma.rn.f32x2 %0, %1, %2, %0;" : "+l"(d) : "l"(a), "l"(b));
}
__device__ __forceinline__ float pairsum(unsigned long long v) {
    return __uint_as_float((unsigned)v) + __uint_as_float((unsigned)(v >> 32));
}

// ============================================================
// QKV projection (FFMA2)  [8192x512]@[512x1536] -> g_Q,g_K,g_V
// ============================================================
__global__ __launch_bounds__(256, 2) void qkv_proj_kernel(
    const float* __restrict__ Zq, const float* __restrict__ Zkv,
    const float* __restrict__ W)
{
    const int m0   = blockIdx.x * 64;
    const int n0   = blockIdx.y * 64;
    const int part = n0 >> 9;
    const float* A = (part == 0) ? Zq : Zkv;
    float* dst = (part == 0) ? g_Q : (part == 1) ? g_K : g_V;
    const int dcol0 = n0 - (part << 9);

    __shared__ float As[64][66];
    __shared__ float Bs[64][66];

    const int t = threadIdx.x, tx = t & 15, ty = t >> 4;
    unsigned long long acc[4][4] = {};

    for (int kt = 0; kt < 512; kt += 64) {
        __syncthreads();
        #pragma unroll
        for (int i = 0; i < 8; i++) {
            int idx = t + i * 256;
            int r = idx >> 5, c2 = (idx & 31) << 1;
            *(float2*)&As[r][c2] =
                *(const float2*)(A + (size_t)(m0 + r) * 512 + kt + c2);
        }
        #pragma unroll
        for (int i = 0; i < 4; i++) {
            int idx = t + i * 256;
            int kr = idx >> 4, nc = (idx & 15) << 2;
            float4 w = *(const float4*)(W + (size_t)(kt + kr) * 1536 + n0 + nc);
            Bs[nc + 0][kr] = w.x; Bs[nc + 1][kr] = w.y;
            Bs[nc + 2][kr] = w.z; Bs[nc + 3][kr] = w.w;
        }
        __syncthreads();
        #pragma unroll 8
        for (int kk = 0; kk < 32; kk++) {
            unsigned long long a2[4], b2[4];
            #pragma unroll
            for (int i = 0; i < 4; i++)
                a2[i] = *(const unsigned long long*)&As[ty + 16 * i][kk << 1];
            #pragma unroll
            for (int j = 0; j < 4; j++)
                b2[j] = *(const unsigned long long*)&Bs[tx + 16 * j][kk << 1];
            #pragma unroll
            for (int i = 0; i < 4; i++)
                #pragma unroll
                for (int j = 0; j < 4; j++)
                    ffma2(acc[i][j], a2[i], b2[j]);
        }
    }

    #pragma unroll
    for (int i = 0; i < 4; i++) {
        const int m  = m0 + ty + 16 * i;
        const int bb = m >> 11, ss = m & 2047;
        #pragma unroll
        for (int j = 0; j < 4; j++) {
            const int d  = dcol0 + tx + 16 * j;
            const int hh = d >> 6, dk = d & 63;
            dst[(((size_t)bb * H + hh) * S + ss) * DK + dk] = pairsum(acc[i][j]);
        }
    }
}

// ============================================================
// scores = Q@K^T*scale + mask via tf32 mma.sync (3x split),
// fused per-thread online softmax stats.
// block: 256 thr (8 warps). q-strip 128 rows, k chunks of 64.
// ============================================================
__global__ __launch_bounds__(256) void scores_mma_kernel(const float* __restrict__ mask)
{
    __shared__ float Qs[128 * 68];          // staging; reused as Khi/Klo
    float* Kh = Qs;                          // [64][68]
    float* Kl = Qs + 64 * 68;                // [64][68]

    const int t = threadIdx.x, w = t >> 5, lane = t & 31;
    const int r = lane >> 2, c = lane & 3;
    const int bh = blockIdx.y, q0 = blockIdx.x * 128;
    const float* Qb = g_Q + ((size_t)bh * S + q0) * DK;
    const float* Kb = g_K + (size_t)bh * S * DK;
    float* Sp = g_Sc + (size_t)bh * S * S;

    // stage Q tile [128][64]
    #pragma unroll
    for (int i = 0; i < 8; i++) {
        int idx = t + i * 256;
        int row = idx >> 4, c4 = (idx & 15) << 2;
        *(float4*)&Qs[row * 68 + c4] = *(const float4*)(Qb + row * 64 + c4);
    }
    __syncthreads();

    // extract persistent A fragments (hi/lo tf32)
    uint32_t Ahi[8][4], Alo[8][4];
    #pragma unroll
    for (int ks = 0; ks < 8; ks++)
        #pragma unroll
        for (int i = 0; i < 4; i++) {
            const int row = 16 * w + r + ((i & 1) << 3);
            const int col = ks * 8 + c + ((i >> 1) << 2);
            const float v = Qs[row * 68 + col];
            const float h = tf32f(v);
            Ahi[ks][i] = __float_as_uint(h);
            Alo[ks][i] = __float_as_uint(tf32f(v - h));
        }
    __syncthreads();                         // Qs about to be overwritten

    const int qA = q0 + 16 * w + r, qB = qA + 8;
    float mA = -CUDART_INF_F, lA = 0.f, mB = -CUDART_INF_F, lB = 0.f;

    float4 pf[4];
    #pragma unroll
    for (int i = 0; i < 4; i++) {
        int idx = t + i * 256;
        pf[i] = *(const float4*)(Kb + (size_t)(idx >> 4) * 64 + ((idx & 15) << 2));
    }

    for (int kc = 0; kc < 32; kc++) {
        // stage K chunk hi/lo
        #pragma unroll
        for (int i = 0; i < 4; i++) {
            int idx = t + i * 256;
            int row = idx >> 4, c4 = (idx & 15) << 2;
            float4 v = pf[i], h, l;
            h.x = tf32f(v.x); l.x = tf32f(v.x - h.x);
            h.y = tf32f(v.y); l.y = tf32f(v.y - h.y);
            h.z = tf32f(v.z); l.z = tf32f(v.z - h.z);
            h.w = tf32f(v.w); l.w = tf32f(v.w - h.w);
            *(float4*)&Kh[row * 68 + c4] = h;
            *(float4*)&Kl[row * 68 + c4] = l;
        }
        __syncthreads();
        if (kc < 31) {
            #pragma unroll
            for (int i = 0; i < 4; i++) {
                int idx = t + i * 256;
                pf[i] = *(const float4*)(Kb +
                    (size_t)((kc + 1) * 64 + (idx >> 4)) * 64 + ((idx & 15) << 2));
            }
        }
        const int kt = kc * 64;
        #pragma unroll
        for (int nt = 0; nt < 8; nt++) {
            float d0 = 0.f, d1 = 0.f, d2 = 0.f, d3 = 0.f;
            #pragma unroll
            for (int ks = 0; ks < 8; ks++) {
                const int ba = (nt * 8 + r) * 68 + ks * 8 + c;
                const uint32_t bh0 = __float_as_uint(Kh[ba]);
                const uint32_t bh1 = __float_as_uint(Kh[ba + 4]);
                const uint32_t bl0 = __float_as_uint(Kl[ba]);
                const uint32_t bl1 = __float_as_uint(Kl[ba + 4]);
                mma8(d0, d1, d2, d3, Ahi[ks][0], Ahi[ks][1], Ahi[ks][2], Ahi[ks][3], bh0, bh1);
                mma8(d0, d1, d2, d3, Ahi[ks][0], Ahi[ks][1], Ahi[ks][2], Ahi[ks][3], bl0, bl1);
                mma8(d0, d1, d2, d3, Alo[ks][0], Alo[ks][1], Alo[ks][2], Alo[ks][3], bh0, bh1);
            }
            const int col = kt + nt * 8 + 2 * c;
            const float2 mk0 = *(const float2*)(mask + (size_t)qA * S + col);
            const float2 mk1 = *(const float2*)(mask + (size_t)qB * S + col);
            const float v0 = fmaf(d0, SCALE, mk0.x), v1 = fmaf(d1, SCALE, mk0.y);
            const float v2 = fmaf(d2, SCALE, mk1.x), v3 = fmaf(d3, SCALE, mk1.y);
            float2 s01 = {v0, v1}, s23 = {v2, v3};
            *(float2*)(Sp + (size_t)qA * S + col) = s01;
            *(float2*)(Sp + (size_t)qB * S + col) = s23;
            onl(mA, lA, v0, v1);
            onl(mB, lB, v2, v3);
        }
        __syncthreads();
    }

    merge_sh(mA, lA, 1); merge_sh(mA, lA, 2);
    merge_sh(mB, lB, 1); merge_sh(mB, lB, 2);
    if (c == 0) {
        g_M[bh * S + qA] = mA; g_Li[bh * S + qA] = 1.f / lA;
        g_M[bh * S + qB] = mB; g_Li[bh * S + qB] = 1.f / lB;
    }
}

// ============================================================
// ctx = softmax(S) @ V via tf32 mma.sync (P hi/lo x V hi/lo, 3 terms).
// block: 256 thr, q-strip 128, contraction chunks of 64.
// ============================================================
__global__ __launch_bounds__(256) void ctx_mma_kernel()
{
    __shared__ float Vh[64 * 72];
    __shared__ float Vl[64 * 72];

    const int t = threadIdx.x, w = t >> 5, lane = t & 31;
    const int r = lane >> 2, c = lane & 3;
    const int bh = blockIdx.y, q0 = blockIdx.x * 128;
    const int b = bh >> 3, h = bh & 7;
    const float* Sp = g_Sc + (size_t)bh * S * S;
    const float* Vb = g_V + (size_t)bh * S * DK;

    const int qA = q0 + 16 * w + r, qB = qA + 8;
    const float mAv = g_M[bh * S + qA], liA = g_Li[bh * S + qA];
    const float mBv = g_M[bh * S + qB], liB = g_Li[bh * S + qB];

    float acc[8][4] = {};

    float4 pf[4];
    #pragma unroll
    for (int i = 0; i < 4; i++) {
        int idx = t + i * 256;
        pf[i] = *(const float4*)(Vb + (size_t)(idx >> 4) * 64 + ((idx & 15) << 2));
    }

    for (int kc = 0; kc < 32; kc++) {
        __syncthreads();
        #pragma unroll
        for (int i = 0; i < 4; i++) {
            int idx = t + i * 256;
            int row = idx >> 4, c4 = (idx & 15) << 2;
            float4 v = pf[i], hi, lo;
            hi.x = tf32f(v.x); lo.x = tf32f(v.x - hi.x);
            hi.y = tf32f(v.y); lo.y = tf32f(v.y - hi.y);
            hi.z = tf32f(v.z); lo.z = tf32f(v.z - hi.z);
            hi.w = tf32f(v.w); lo.w = tf32f(v.w - hi.w);
            *(float4*)&Vh[row * 72 + c4] = hi;
            *(float4*)&Vl[row * 72 + c4] = lo;
        }
        __syncthreads();
        if (kc < 31) {
            #pragma unroll
            for (int i = 0; i < 4; i++) {
                int idx = t + i * 256;
                pf[i] = *(const float4*)(Vb +
                    (size_t)((kc + 1) * 64 + (idx >> 4)) * 64 + ((idx & 15) << 2));
            }
        }
        const int kt = kc * 64;
        #pragma unroll
        for (int ks = 0; ks < 8; ks++) {
            const int k0 = kt + ks * 8 + c;
            const float s0 = Sp[(size_t)qA * S + k0];
            const float s1 = Sp[(size_t)qB * S + k0];
            const float s2 = Sp[(size_t)qA * S + k0 + 4];
            const float s3 = Sp[(size_t)qB * S + k0 + 4];
            const float p0 = __expf(s0 - mAv) * liA;
            const float p1 = __expf(s1 - mBv) * liB;
            const float p2 = __expf(s2 - mAv) * liA;
            const float p3 = __expf(s3 - mBv) * liB;
            uint32_t Ph[4], Pl[4];
            float hh;
            hh = tf32f(p0); Ph[0] = __float_as_uint(hh); Pl[0] = __float_as_uint(tf32f(p0 - hh));
            hh = tf32f(p1); Ph[1] = __float_as_uint(hh); Pl[1] = __float_as_uint(tf32f(p1 - hh));
            hh = tf32f(p2); Ph[2] = __float_as_uint(hh); Pl[2] = __float_as_uint(tf32f(p2 - hh));
            hh = tf32f(p3); Ph[3] = __float_as_uint(hh); Pl[3] = __float_as_uint(tf32f(p3 - hh));
            #pragma unroll
            for (int nt = 0; nt < 8; nt++) {
                const int ba = (ks * 8 + c) * 72 + nt * 8 + r;
                const uint32_t bh0 = __float_as_uint(Vh[ba]);
                const uint32_t bh1 = __float_as_uint(Vh[ba + 4 * 72]);
                const uint32_t bl0 = __float_as_uint(Vl[ba]);
                const uint32_t bl1 = __float_as_uint(Vl[ba + 4 * 72]);
                mma8(acc[nt][0], acc[nt][1], acc[nt][2], acc[nt][3],
                     Ph[0], Ph[1], Ph[2], Ph[3], bh0, bh1);
                mma8(acc[nt][0], acc[nt][1], acc[nt][2], acc[nt][3],
                     Ph[0], Ph[1], Ph[2], Ph[3], bl0, bl1);
                mma8(acc[nt][0], acc[nt][1], acc[nt][2], acc[nt][3],
                     Pl[0], Pl[1], Pl[2], Pl[3], bh0, bh1);
            }
        }
    }

    #pragma unroll
    for (int nt = 0; nt < 8; nt++) {
        const int col = h * 64 + nt * 8 + 2 * c;
        float2 oA = {acc[nt][0], acc[nt][1]};
        float2 oB = {acc[nt][2], acc[nt][3]};
        *(float2*)(g_Ctx + ((size_t)b * S + qA) * 512 + col) = oA;
        *(float2*)(g_Ctx + ((size_t)b * S + qB) * 512 + col) = oB;
    }
}

// ============================================================
// attn.mean over heads, recomputing probs from raw scores.
// ============================================================
__global__ __launch_bounds__(256) void mean_kernel(float* __restrict__ mean)
{
    const size_t i4 = (size_t)blockIdx.x * 256 + threadIdx.x;   // < B*S*S/4
    const size_t per_b = (size_t)S * S / 4;
    const int bb = (int)(i4 / per_b);
    const size_t r4 = i4 - (size_t)bb * per_b;
    const int q  = (int)(r4 / (S / 4));
    const int k4 = (int)(r4 % (S / 4)) * 4;

    float4 acc = {0.f, 0.f, 0.f, 0.f};
    #pragma unroll
    for (int hh = 0; hh < H; hh++) {
        const int row = (bb * H + hh) * S + q;
        const float m  = __ldg(&g_M[row]);
        const float li = __ldg(&g_Li[row]);
        const float4 s = *(const float4*)(g_Sc + (size_t)row * S + k4);
        acc.x += __expf(s.x - m) * li;
        acc.y += __expf(s.y - m) * li;
        acc.z += __expf(s.z - m) * li;
        acc.w += __expf(s.w - m) * li;
    }
    acc.x *= 0.125f; acc.y *= 0.125f; acc.z *= 0.125f; acc.w *= 0.125f;
    ((float4*)mean)[i4] = acc;
}

// ============================================================
// out = Ctx @ Wout (FFMA2)
// ============================================================
__global__ __launch_bounds__(256, 2) void out_proj_kernel(
    const float* __restrict__ W, float* __restrict__ out)
{
    const int m0 = blockIdx.x * 64;
    const int n0 = blockIdx.y * 64;

    __shared__ float As[64][66];
    __shared__ float Bs[64][66];

    const int t = threadIdx.x, tx = t & 15, ty = t >> 4;
    unsigned long long acc[4][4] = {};

    for (int kt = 0; kt < 512; kt += 64) {
        __syncthreads();
        #pragma unroll
        for (int i = 0; i < 8; i++) {
            int idx = t + i * 256;
            int r = idx >> 5, c2 = (idx & 31) << 1;
            *(float2*)&As[r][c2] =
                *(const float2*)(g_Ctx + (size_t)(m0 + r) * 512 + kt + c2);
        }
        #pragma unroll
        for (int i = 0; i < 4; i++) {
            int idx = t + i * 256;
            int kr = idx >> 4, nc = (idx & 15) << 2;
            float4 w = *(const float4*)(W + (size_t)(kt + kr) * 512 + n0 + nc);
            Bs[nc + 0][kr] = w.x; Bs[nc + 1][kr] = w.y;
            Bs[nc + 2][kr] = w.z; Bs[nc + 3][kr] = w.w;
        }
        __syncthreads();
        #pragma unroll 8
        for (int kk = 0; kk < 32; kk++) {
            unsigned long long a2[4], b2[4];
            #pragma unroll
            for (int i = 0; i < 4; i++)
                a2[i] = *(const unsigned long long*)&As[ty + 16 * i][kk << 1];
            #pragma unroll
            for (int j = 0; j < 4; j++)
                b2[j] = *(const unsigned long long*)&Bs[tx + 16 * j][kk << 1];
            #pragma unroll
            for (int i = 0; i < 4; i++)
                #pragma unroll
                for (int j = 0; j < 4; j++)
                    ffma2(acc[i][j], a2[i], b2[j]);
        }
    }

    #pragma unroll
    for (int i = 0; i < 4; i++)
        #pragma unroll
        for (int j = 0; j < 4; j++)
            out[(size_t)(m0 + ty + 16 * i) * 512 + n0 + tx + 16 * j] =
                pairsum(acc[i][j]);
}

// ============================================================
extern "C" void kernel_launch(void* const* d_in, const int* in_sizes, int n_in,
                              void* d_out, int out_size)
{
    const float* Zq   = (const float*)d_in[0];
    const float* Zkv  = (const float*)d_in[1];
    const float* mask = (const float*)d_in[2];
    const float* Wqkv = (const float*)d_in[3];
    const float* Wout = (const float*)d_in[4];

    float* out  = (float*)d_out;                 // [B,S,D]
    float* mean = out + (size_t)B * S * D;       // [B,S,S]

    qkv_proj_kernel<<<dim3(128, 24), 256>>>(Zq, Zkv, Wqkv);
    scores_mma_kernel<<<dim3(16, 32), 256>>>(mask);
    ctx_mma_kernel<<<dim3(16, 32), 256>>>();
    mean_kernel<<<(B * (size_t)S * S / 4) / 256, 256>>>(mean);
    out_proj_kernel<<<dim3(128, 8), 256>>>(Wout, out);
}

// round 11
// speedup vs baseline: 2.5942x; 1.1843x over previous
#include <cuda_runtime.h>
#include <cuda_fp16.h>
#include <math_constants.h>
#include <cstdint>

static constexpr int B  = 4;
static constexpr int S  = 2048;
static constexpr int D  = 512;
static constexpr int H  = 8;
static constexpr int DK = 64;
static constexpr int BH = B * H;            // 32
static constexpr float SCALE = 0.125f;      // DK^-0.5

// ---- scratch (device globals; no runtime allocation allowed) ----
__device__ float g_Q[B * H * S * DK];       // 16 MB  [bh][s][dk]
__device__ float g_K[B * H * S * DK];       // 16 MB  [bh][s][dk]
__device__ float g_Vt[B * H * DK * S];      // 16 MB  [bh][dk][s]
__device__ float g_Ctx[B * S * D];          // 16 MB  [b][s][h*64+dk]
__device__ float g_Sc[(size_t)BH * S * S];  // 512 MB raw masked scores
__device__ float g_M[BH * S];               // row max
__device__ float g_Li[BH * S];              // 1 / row sum

// ============================================================
// helpers
// ============================================================
// m16n8k16 row.col f32.f16.f16.f32 warp MMA
__device__ __forceinline__ void mma16(float* d, const uint32_t* a,
                                      uint32_t b0, uint32_t b1) {
    asm("mma.sync.aligned.m16n8k16.row.col.f32.f16.f16.f32 "
        "{%0,%1,%2,%3}, {%4,%5,%6,%7}, {%8,%9}, {%0,%1,%2,%3};"
        : "+f"(d[0]), "+f"(d[1]), "+f"(d[2]), "+f"(d[3])
        : "r"(a[0]), "r"(a[1]), "r"(a[2]), "r"(a[3]), "r"(b0), "r"(b1));
}

// split a pair of floats into packed fp16 hi + lo halves
__device__ __forceinline__ void split2(float x, float y, uint32_t& hi, uint32_t& lo) {
    half2 h = __floats2half2_rn(x, y);
    half2 l = __floats2half2_rn(x - __low2float(h), y - __high2float(h));
    hi = *reinterpret_cast<uint32_t*>(&h);
    lo = *reinterpret_cast<uint32_t*>(&l);
}

// convert float4 (k-contiguous) into two half2 hi + two half2 lo at smem offset
__device__ __forceinline__ void cvt_store4(half* hb, half* lb, int off, float4 v) {
    uint32_t h0, l0, h1, l1;
    split2(v.x, v.y, h0, l0);
    split2(v.z, v.w, h1, l1);
    *reinterpret_cast<uint32_t*>(hb + off)     = h0;
    *reinterpret_cast<uint32_t*>(hb + off + 2) = h1;
    *reinterpret_cast<uint32_t*>(lb + off)     = l0;
    *reinterpret_cast<uint32_t*>(lb + off + 2) = l1;
}

// online softmax update with two new values
__device__ __forceinline__ void onl(float& m, float& l, float v0, float v1) {
    const float vm = fmaxf(v0, v1);
    const float mn = fmaxf(m, vm);
    l = l * __expf(m - mn) + __expf(v0 - mn) + __expf(v1 - mn);
    m = mn;
}
__device__ __forceinline__ void merge_sh(float& m, float& l, int off) {
    const float mo = __shfl_xor_sync(0xffffffffu, m, off);
    const float lo = __shfl_xor_sync(0xffffffffu, l, off);
    const float mn = fmaxf(m, mo);
    l = l * __expf(m - mn) + lo * __expf(mo - mn);
    m = mn;
}

static constexpr int LDH = 72;   // half stride for [row][k] half tiles

// ============================================================
// QKV projection via fp16 mma (3-term split)
// block 128 thr (4 warps), M-strip 64, N tile 64, K chunks 64.
// grid (8192/64, 1536/64) = (128, 24)
// ============================================================
__global__ __launch_bounds__(128) void qkv_mma_kernel(
    const float* __restrict__ Zq, const float* __restrict__ Zkv,
    const float* __restrict__ W)
{
    __shared__ half Ah[64 * LDH], Al[64 * LDH];
    __shared__ half Bh[64 * LDH], Bl[64 * LDH];

    const int t = threadIdx.x, w = t >> 5, lane = t & 31;
    const int r = lane >> 2, c = lane & 3;
    const int m0 = blockIdx.x * 64;
    const int n0 = blockIdx.y * 64;
    const int part = n0 >> 9;
    const float* A = (part == 0) ? Zq : Zkv;
    const int dcol0 = n0 - (part << 9);

    float acc[8][4] = {};

    for (int kt = 0; kt < 512; kt += 64) {
        __syncthreads();
        // stage A chunk [64m][64k]
        #pragma unroll
        for (int i = 0; i < 8; i++) {
            int idx = t + i * 128;
            int row = idx >> 4, c4 = (idx & 15) << 2;
            float4 v = *(const float4*)(A + (size_t)(m0 + row) * 512 + kt + c4);
            cvt_store4(Ah, Al, row * LDH + c4, v);
        }
        // stage B chunk: W[kt..][n0..] transposed to [n][k]
        #pragma unroll
        for (int i = 0; i < 8; i++) {
            int idx = t + i * 128;
            int kr = idx >> 4, nc = (idx & 15) << 2;
            float4 v = *(const float4*)(W + (size_t)(kt + kr) * 1536 + n0 + nc);
            #pragma unroll
            for (int j = 0; j < 4; j++) {
                float x = (j == 0) ? v.x : (j == 1) ? v.y : (j == 2) ? v.z : v.w;
                half hv = __float2half_rn(x);
                Bh[(nc + j) * LDH + kr] = hv;
                Bl[(nc + j) * LDH + kr] = __float2half_rn(x - __half2float(hv));
            }
        }
        __syncthreads();

        #pragma unroll
        for (int ks = 0; ks < 4; ks++) {
            uint32_t ahi[4], alo[4];
            const int kb = ks * 16 + 2 * c;
            #pragma unroll
            for (int i = 0; i < 4; i++) {
                const int row = 16 * w + r + ((i & 1) << 3);
                const int col = kb + ((i >> 1) << 3);
                ahi[i] = *reinterpret_cast<const uint32_t*>(Ah + row * LDH + col);
                alo[i] = *reinterpret_cast<const uint32_t*>(Al + row * LDH + col);
            }
            #pragma unroll
            for (int nt = 0; nt < 8; nt++) {
                const int bb = (nt * 8 + r) * LDH + kb;
                const uint32_t bh0 = *reinterpret_cast<const uint32_t*>(Bh + bb);
                const uint32_t bh1 = *reinterpret_cast<const uint32_t*>(Bh + bb + 8);
                const uint32_t bl0 = *reinterpret_cast<const uint32_t*>(Bl + bb);
                const uint32_t bl1 = *reinterpret_cast<const uint32_t*>(Bl + bb + 8);
                mma16(acc[nt], ahi, bh0, bh1);
                mma16(acc[nt], ahi, bl0, bl1);
                mma16(acc[nt], alo, bh0, bh1);
            }
        }
    }

    // epilogue: scatter into g_Q / g_K / g_Vt
    const int mA = m0 + 16 * w + r, mB = mA + 8;
    #pragma unroll
    for (int nt = 0; nt < 8; nt++) {
        const int d = dcol0 + nt * 8 + 2 * c;
        const int hh = d >> 6, dk = d & 63;
        #pragma unroll
        for (int half_m = 0; half_m < 2; half_m++) {
            const int m = half_m ? mB : mA;
            const int bb = m >> 11, ss = m & 2047;
            const float d0 = acc[nt][2 * half_m], d1 = acc[nt][2 * half_m + 1];
            if (part == 2) {
                float* vp = g_Vt + (((size_t)bb * H + hh) * DK + dk) * S + ss;
                vp[0] = d0;
                vp[S] = d1;
            } else {
                float* qp = ((part == 0) ? g_Q : g_K) +
                            (((size_t)bb * H + hh) * S + ss) * DK + dk;
                float2 o = {d0, d1};
                *(float2*)qp = o;
            }
        }
    }
}

// ============================================================
// scores = Q@K^T*scale + mask via fp16 mma (3-term), fused
// online softmax stats. block 128 thr, q-strip 64, k chunks 64.
// grid (32, 32)
// ============================================================
__global__ __launch_bounds__(128) void scores_mma_kernel(const float* __restrict__ mask)
{
    __shared__ float Qs[64 * 68];
    __shared__ half Kh[64 * LDH], Kl[64 * LDH];

    const int t = threadIdx.x, w = t >> 5, lane = t & 31;
    const int r = lane >> 2, c = lane & 3;
    const int bh = blockIdx.y, q0 = blockIdx.x * 64;
    const float* Qb = g_Q + ((size_t)bh * S + q0) * DK;
    const float* Kb = g_K + (size_t)bh * S * DK;
    float* Sp = g_Sc + (size_t)bh * S * S;

    // stage Q strip [64][64] fp32, then extract persistent hi/lo frags
    #pragma unroll
    for (int i = 0; i < 8; i++) {
        int idx = t + i * 128;
        int row = idx >> 4, c4 = (idx & 15) << 2;
        *(float4*)&Qs[row * 68 + c4] = *(const float4*)(Qb + row * 64 + c4);
    }
    __syncthreads();

    uint32_t Ahi[4][4], Alo[4][4];
    #pragma unroll
    for (int ks = 0; ks < 4; ks++)
        #pragma unroll
        for (int i = 0; i < 4; i++) {
            const int row = 16 * w + r + ((i & 1) << 3);
            const int col = ks * 16 + 2 * c + ((i >> 1) << 3);
            split2(Qs[row * 68 + col], Qs[row * 68 + col + 1],
                   Ahi[ks][i], Alo[ks][i]);
        }

    const int qA = q0 + 16 * w + r, qB = qA + 8;
    float mA = -CUDART_INF_F, lA = 0.f, mB = -CUDART_INF_F, lB = 0.f;

    for (int kc = 0; kc < 32; kc++) {
        __syncthreads();
        #pragma unroll
        for (int i = 0; i < 8; i++) {
            int idx = t + i * 128;
            int row = idx >> 4, c4 = (idx & 15) << 2;
            float4 v = *(const float4*)(Kb + (size_t)(kc * 64 + row) * 64 + c4);
            cvt_store4(Kh, Kl, row * LDH + c4, v);
        }
        __syncthreads();

        const int kt = kc * 64;
        #pragma unroll
        for (int nt = 0; nt < 8; nt++) {
            float d[4] = {};
            #pragma unroll
            for (int ks = 0; ks < 4; ks++) {
                const int bb = (nt * 8 + r) * LDH + ks * 16 + 2 * c;
                const uint32_t bh0 = *reinterpret_cast<const uint32_t*>(Kh + bb);
                const uint32_t bh1 = *reinterpret_cast<const uint32_t*>(Kh + bb + 8);
                const uint32_t bl0 = *reinterpret_cast<const uint32_t*>(Kl + bb);
                const uint32_t bl1 = *reinterpret_cast<const uint32_t*>(Kl + bb + 8);
                mma16(d, Ahi[ks], bh0, bh1);
                mma16(d, Ahi[ks], bl0, bl1);
                mma16(d, Alo[ks], bh0, bh1);
            }
            const int col = kt + nt * 8 + 2 * c;
            const float2 mk0 = *(const float2*)(mask + (size_t)qA * S + col);
            const float2 mk1 = *(const float2*)(mask + (size_t)qB * S + col);
            const float v0 = fmaf(d[0], SCALE, mk0.x), v1 = fmaf(d[1], SCALE, mk0.y);
            const float v2 = fmaf(d[2], SCALE, mk1.x), v3 = fmaf(d[3], SCALE, mk1.y);
            float2 s01 = {v0, v1}, s23 = {v2, v3};
            *(float2*)(Sp + (size_t)qA * S + col) = s01;
            *(float2*)(Sp + (size_t)qB * S + col) = s23;
            onl(mA, lA, v0, v1);
            onl(mB, lB, v2, v3);
        }
    }

    merge_sh(mA, lA, 1); merge_sh(mA, lA, 2);
    merge_sh(mB, lB, 1); merge_sh(mB, lB, 2);
    if (c == 0) {
        g_M[bh * S + qA] = mA; g_Li[bh * S + qA] = 1.f / lA;
        g_M[bh * S + qB] = mB; g_Li[bh * S + qB] = 1.f / lB;
    }
}

// ============================================================
// ctx = softmax(S) @ V via fp16 mma (3-term: Ph*Vh + Ph*Vl + Pl*Vh).
// block 128 thr, q-strip 64, contraction chunks 64. grid (32, 32)
// ============================================================
__global__ __launch_bounds__(128) void ctx_mma_kernel()
{
    __shared__ half Vh[64 * LDH], Vl[64 * LDH];

    const int t = threadIdx.x, w = t >> 5, lane = t & 31;
    const int r = lane >> 2, c = lane & 3;
    const int bh = blockIdx.y, q0 = blockIdx.x * 64;
    const int b = bh >> 3, h = bh & 7;
    const float* Sp = g_Sc + (size_t)bh * S * S;
    const float* Vt = g_Vt + (size_t)bh * DK * S;   // [dk][s]

    const int qA = q0 + 16 * w + r, qB = qA + 8;
    const float mAv = g_M[bh * S + qA], liA = g_Li[bh * S + qA];
    const float mBv = g_M[bh * S + qB], liB = g_Li[bh * S + qB];

    float acc[8][4] = {};

    for (int kc = 0; kc < 32; kc++) {
        __syncthreads();
        // stage V^T chunk [64 dk][64 s] -> hi/lo halves (straight copy)
        #pragma unroll
        for (int i = 0; i < 8; i++) {
            int idx = t + i * 128;
            int row = idx >> 4, c4 = (idx & 15) << 2;
            float4 v = *(const float4*)(Vt + (size_t)row * S + kc * 64 + c4);
            cvt_store4(Vh, Vl, row * LDH + c4, v);
        }
        __syncthreads();

        const int kt = kc * 64;
        #pragma unroll
        for (int ks = 0; ks < 4; ks++) {
            const int k0 = kt + ks * 16 + 2 * c;
            const float2 sA0 = *(const float2*)(Sp + (size_t)qA * S + k0);
            const float2 sB0 = *(const float2*)(Sp + (size_t)qB * S + k0);
            const float2 sA1 = *(const float2*)(Sp + (size_t)qA * S + k0 + 8);
            const float2 sB1 = *(const float2*)(Sp + (size_t)qB * S + k0 + 8);
            uint32_t Ph[4], Pl[4];
            split2(__expf(sA0.x - mAv) * liA, __expf(sA0.y - mAv) * liA, Ph[0], Pl[0]);
            split2(__expf(sB0.x - mBv) * liB, __expf(sB0.y - mBv) * liB, Ph[1], Pl[1]);
            split2(__expf(sA1.x - mAv) * liA, __expf(sA1.y - mAv) * liA, Ph[2], Pl[2]);
            split2(__expf(sB1.x - mBv) * liB, __expf(sB1.y - mBv) * liB, Ph[3], Pl[3]);
            #pragma unroll
            for (int nt = 0; nt < 8; nt++) {
                const int bb = (nt * 8 + r) * LDH + ks * 16 + 2 * c;
                const uint32_t bh0 = *reinterpret_cast<const uint32_t*>(Vh + bb);
                const uint32_t bh1 = *reinterpret_cast<const uint32_t*>(Vh + bb + 8);
                const uint32_t bl0 = *reinterpret_cast<const uint32_t*>(Vl + bb);
                const uint32_t bl1 = *reinterpret_cast<const uint32_t*>(Vl + bb + 8);
                mma16(acc[nt], Ph, bh0, bh1);
                mma16(acc[nt], Ph, bl0, bl1);
                mma16(acc[nt], Pl, bh0, bh1);
            }
        }
    }

    #pragma unroll
    for (int nt = 0; nt < 8; nt++) {
        const int col = h * 64 + nt * 8 + 2 * c;
        float2 oA = {acc[nt][0], acc[nt][1]};
        float2 oB = {acc[nt][2], acc[nt][3]};
        *(float2*)(g_Ctx + ((size_t)b * S + qA) * 512 + col) = oA;
        *(float2*)(g_Ctx + ((size_t)b * S + qB) * 512 + col) = oB;
    }
}

// ============================================================
// attn.mean over heads, recomputing probs from raw scores.
// ============================================================
__global__ __launch_bounds__(256) void mean_kernel(float* __restrict__ mean)
{
    const size_t i4 = (size_t)blockIdx.x * 256 + threadIdx.x;   // < B*S*S/4
    const size_t per_b = (size_t)S * S / 4;
    const int bb = (int)(i4 / per_b);
    const size_t r4 = i4 - (size_t)bb * per_b;
    const int q  = (int)(r4 / (S / 4));
    const int k4 = (int)(r4 % (S / 4)) * 4;

    float4 acc = {0.f, 0.f, 0.f, 0.f};
    #pragma unroll
    for (int hh = 0; hh < H; hh++) {
        const int row = (bb * H + hh) * S + q;
        const float m  = __ldg(&g_M[row]);
        const float li = __ldg(&g_Li[row]);
        const float4 s = *(const float4*)(g_Sc + (size_t)row * S + k4);
        acc.x += __expf(s.x - m) * li;
        acc.y += __expf(s.y - m) * li;
        acc.z += __expf(s.z - m) * li;
        acc.w += __expf(s.w - m) * li;
    }
    acc.x *= 0.125f; acc.y *= 0.125f; acc.z *= 0.125f; acc.w *= 0.125f;
    ((float4*)mean)[i4] = acc;
}

// ============================================================
// out = Ctx @ Wout via fp16 mma (3-term). grid (128, 8), 128 thr.
// ============================================================
__global__ __launch_bounds__(128) void out_mma_kernel(
    const float* __restrict__ W, float* __restrict__ out)
{
    __shared__ half Ah[64 * LDH], Al[64 * LDH];
    __shared__ half Bh[64 * LDH], Bl[64 * LDH];

    const int t = threadIdx.x, w = t >> 5, lane = t & 31;
    const int r = lane >> 2, c = lane & 3;
    const int m0 = blockIdx.x * 64;
    const int n0 = blockIdx.y * 64;

    float acc[8][4] = {};

    for (int kt = 0; kt < 512; kt += 64) {
        __syncthreads();
        #pragma unroll
        for (int i = 0; i < 8; i++) {
            int idx = t + i * 128;
            int row = idx >> 4, c4 = (idx & 15) << 2;
            float4 v = *(const float4*)(g_Ctx + (size_t)(m0 + row) * 512 + kt + c4);
            cvt_store4(Ah, Al, row * LDH + c4, v);
        }
        #pragma unroll
        for (int i = 0; i < 8; i++) {
            int idx = t + i * 128;
            int kr = idx >> 4, nc = (idx & 15) << 2;
            float4 v = *(const float4*)(W + (size_t)(kt + kr) * 512 + n0 + nc);
            #pragma unroll
            for (int j = 0; j < 4; j++) {
                float x = (j == 0) ? v.x : (j == 1) ? v.y : (j == 2) ? v.z : v.w;
                half hv = __float2half_rn(x);
                Bh[(nc + j) * LDH + kr] = hv;
                Bl[(nc + j) * LDH + kr] = __float2half_rn(x - __half2float(hv));
            }
        }
        __syncthreads();

        #pragma unroll
        for (int ks = 0; ks < 4; ks++) {
            uint32_t ahi[4], alo[4];
            const int kb = ks * 16 + 2 * c;
            #pragma unroll
            for (int i = 0; i < 4; i++) {
                const int row = 16 * w + r + ((i & 1) << 3);
                const int col = kb + ((i >> 1) << 3);
                ahi[i] = *reinterpret_cast<const uint32_t*>(Ah + row * LDH + col);
                alo[i] = *reinterpret_cast<const uint32_t*>(Al + row * LDH + col);
            }
            #pragma unroll
            for (int nt = 0; nt < 8; nt++) {
                const int bb = (nt * 8 + r) * LDH + kb;
                const uint32_t bh0 = *reinterpret_cast<const uint32_t*>(Bh + bb);
                const uint32_t bh1 = *reinterpret_cast<const uint32_t*>(Bh + bb + 8);
                const uint32_t bl0 = *reinterpret_cast<const uint32_t*>(Bl + bb);
                const uint32_t bl1 = *reinterpret_cast<const uint32_t*>(Bl + bb + 8);
                mma16(acc[nt], ahi, bh0, bh1);
                mma16(acc[nt], ahi, bl0, bl1);
                mma16(acc[nt], alo, bh0, bh1);
            }
        }
    }

    const int mA = m0 + 16 * w + r, mB = mA + 8;
    #pragma unroll
    for (int nt = 0; nt < 8; nt++) {
        const int col = n0 + nt * 8 + 2 * c;
        float2 oA = {acc[nt][0], acc[nt][1]};
        float2 oB = {acc[nt][2], acc[nt][3]};
        *(float2*)(out + (size_t)mA * 512 + col) = oA;
        *(float2*)(out + (size_t)mB * 512 + col) = oB;
    }
}

// ============================================================
extern "C" void kernel_launch(void* const* d_in, const int* in_sizes, int n_in,
                              void* d_out, int out_size)
{
    const float* Zq   = (const float*)d_in[0];
    const float* Zkv  = (const float*)d_in[1];
    const float* mask = (const float*)d_in[2];
    const float* Wqkv = (const float*)d_in[3];
    const float* Wout = (const float*)d_in[4];

    float* out  = (float*)d_out;                 // [B,S,D]
    float* mean = out + (size_t)B * S * D;       // [B,S,S]

    qkv_mma_kernel<<<dim3(128, 24), 128>>>(Zq, Zkv, Wqkv);
    scores_mma_kernel<<<dim3(32, 32), 128>>>(mask);
    ctx_mma_kernel<<<dim3(32, 32), 128>>>();
    mean_kernel<<<(B * (size_t)S * S / 4) / 256, 256>>>(mean);
    out_mma_kernel<<<dim3(128, 8), 128>>>(Wout, out);
}

// round 14
// speedup vs baseline: 3.5129x; 1.3541x over previous
#include <cuda_runtime.h>
#include <cuda_fp16.h>
#include <math_constants.h>
#include <cstdint>

static constexpr int B  = 4;
static constexpr int S  = 2048;
static constexpr int D  = 512;
static constexpr int H  = 8;
static constexpr int DK = 64;
static constexpr int BH = B * H;            // 32
static constexpr float SCALE = 0.125f;      // DK^-0.5

// ---- scratch (device globals) ----
// pre-split inputs
__device__ half g_Zqh[B * S * D],  g_Zql[B * S * D];     // [8192][512]
__device__ half g_Zkh[B * S * D],  g_Zkl[B * S * D];
__device__ half g_WqTh[3 * D * D], g_WqTl[3 * D * D];    // [1536][512] (n-major)
__device__ half g_WoTh[D * D],     g_WoTl[D * D];        // [512][512]  (n-major)
// split intermediates
__device__ half g_Qh[BH * S * DK], g_Ql[BH * S * DK];    // [bh][s][dk]
__device__ half g_Kh[BH * S * DK], g_Kl[BH * S * DK];    // [bh][s][dk]
__device__ half g_Vth[BH * DK * S], g_Vtl[BH * DK * S];  // [bh][dk][s]
__device__ half g_Ch[B * S * D],   g_Cl[B * S * D];      // [8192][512]
// fp32 scores scratch + softmax stats
__device__ float g_Sc[(size_t)BH * S * S];               // 512 MB
__device__ float g_M[BH * S];
__device__ float g_Li[BH * S];

// ============================================================
// helpers
// ============================================================
__device__ __forceinline__ void mma16(float* d, const uint32_t* a,
                                      uint32_t b0, uint32_t b1) {
    asm("mma.sync.aligned.m16n8k16.row.col.f32.f16.f16.f32 "
        "{%0,%1,%2,%3}, {%4,%5,%6,%7}, {%8,%9}, {%0,%1,%2,%3};"
        : "+f"(d[0]), "+f"(d[1]), "+f"(d[2]), "+f"(d[3])
        : "r"(a[0]), "r"(a[1]), "r"(a[2]), "r"(a[3]), "r"(b0), "r"(b1));
}
__device__ __forceinline__ void split2(float x, float y, uint32_t& hi, uint32_t& lo) {
    half2 h = __floats2half2_rn(x, y);
    half2 l = __floats2half2_rn(x - __low2float(h), y - __high2float(h));
    hi = *reinterpret_cast<uint32_t*>(&h);
    lo = *reinterpret_cast<uint32_t*>(&l);
}
__device__ __forceinline__ void onl(float& m, float& l, float v0, float v1) {
    const float vm = fmaxf(v0, v1);
    const float mn = fmaxf(m, vm);
    l = l * __expf(m - mn) + __expf(v0 - mn) + __expf(v1 - mn);
    m = mn;
}
__device__ __forceinline__ void merge_sh(float& m, float& l, int off) {
    const float mo = __shfl_xor_sync(0xffffffffu, m, off);
    const float lo = __shfl_xor_sync(0xffffffffu, l, off);
    const float mn = fmaxf(m, mo);
    l = l * __expf(m - mn) + lo * __expf(mo - mn);
    m = mn;
}

// scatter one uint4 (8 halves: row n, cols k8..k8+7) into the permuted
// B-fragment layout: word = ((g*33 + (n&7)*4 + p)<<2) + j + lo_off
__device__ __forceinline__ void scat_b(uint32_t* Fw, int n, int k8, uint4 v, int lo_off) {
    const int g    = ((n >> 3) << 2) + (k8 >> 4);
    const int j    = (k8 >> 3) & 1;
    const int base = ((g * 33 + ((n & 7) << 2)) << 2) + j + lo_off;
    Fw[base + 0]  = v.x;
    Fw[base + 4]  = v.y;
    Fw[base + 8]  = v.z;
    Fw[base + 12] = v.w;
}

// ============================================================
// prep: fp32 -> fp16 hi/lo split (elementwise)
// ============================================================
__global__ __launch_bounds__(256) void split_kernel(
    const float4* __restrict__ src, uint2* __restrict__ dh,
    uint2* __restrict__ dl, int n4)
{
    const int i = blockIdx.x * 256 + threadIdx.x;
    if (i >= n4) return;
    float4 v = src[i];
    uint32_t h0, l0, h1, l1;
    split2(v.x, v.y, h0, l0);
    split2(v.z, v.w, h1, l1);
    uint2 ho = {h0, h1}, lo = {l0, l1};
    dh[i] = ho; dl[i] = lo;
}

// prep: transpose [K][N] fp32 -> [N][K] fp16 hi/lo
__global__ __launch_bounds__(256) void tsplit_kernel(
    const float* __restrict__ src, half* __restrict__ dh,
    half* __restrict__ dl, int K, int N)
{
    const int idx = blockIdx.x * 256 + threadIdx.x;   // < (K/8)*N
    if (idx >= (K >> 3) * N) return;
    const int n  = idx % N;
    const int k8 = (idx / N) << 3;
    uint32_t h[4], l[4];
    #pragma unroll
    for (int p = 0; p < 4; p++) {
        float a = src[(size_t)(k8 + 2 * p) * N + n];
        float b = src[(size_t)(k8 + 2 * p + 1) * N + n];
        split2(a, b, h[p], l[p]);
    }
    uint4 hv = {h[0], h[1], h[2], h[3]};
    uint4 lv = {l[0], l[1], l[2], l[3]};
    *(uint4*)(dh + (size_t)n * K + k8) = hv;
    *(uint4*)(dl + (size_t)n * K + k8) = lv;
}

// ============================================================
// QKV projection: [8192x512]@[512x1536] -> split Q,K,V^T
// 128 thr (4 warps), m-strip 64, n-tile 64, k chunks 64.
// ============================================================
__global__ __launch_bounds__(128) void qkv_mma_kernel()
{
    __shared__ __align__(16) half Ast[2][64 * 72];     // hi, lo  (18432 B)
    __shared__ uint4 FragB[8 * 4 * 33];                // 16896 B
    uint32_t* Fw = (uint32_t*)FragB;

    const int t = threadIdx.x, w = t >> 5, lane = t & 31;
    const int r = lane >> 2, c = lane & 3;
    const int m0 = blockIdx.x * 64;
    const int n0 = blockIdx.y * 64;
    const int part = n0 >> 9;
    const half* Ah_g = (part == 0) ? g_Zqh : g_Zkh;
    const half* Al_g = (part == 0) ? g_Zql : g_Zkl;
    const int dcol0 = n0 - (part << 9);

    float acc[8][4] = {};

    for (int kt = 0; kt < 512; kt += 64) {
        __syncthreads();
        // stage A chunk (pure copies)
        #pragma unroll
        for (int i = 0; i < 4; i++) {
            int idx = t + i * 128;
            int row = idx >> 3, k8 = (idx & 7) << 3;
            *(uint4*)&Ast[0][row * 72 + k8] =
                *(const uint4*)(Ah_g + (size_t)(m0 + row) * 512 + kt + k8);
            *(uint4*)&Ast[1][row * 72 + k8] =
                *(const uint4*)(Al_g + (size_t)(m0 + row) * 512 + kt + k8);
        }
        // stage B chunk into permuted fragment layout
        #pragma unroll
        for (int i = 0; i < 4; i++) {
            int idx = t + i * 128;
            int n = idx >> 3, k8 = (idx & 7) << 3;
            uint4 vh = *(const uint4*)(g_WqTh + (size_t)(n0 + n) * 512 + kt + k8);
            uint4 vl = *(const uint4*)(g_WqTl + (size_t)(n0 + n) * 512 + kt + k8);
            scat_b(Fw, n, k8, vh, 0);
            scat_b(Fw, n, k8, vl, 2);
        }
        __syncthreads();

        #pragma unroll
        for (int ks = 0; ks < 4; ks++) {
            uint32_t ahi[4], alo[4];
            #pragma unroll
            for (int i = 0; i < 4; i++) {
                const int row = 16 * w + r + ((i & 1) << 3);
                const int col = ks * 16 + 2 * c + ((i >> 1) << 3);
                ahi[i] = *(const uint32_t*)&Ast[0][row * 72 + col];
                alo[i] = *(const uint32_t*)&Ast[1][row * 72 + col];
            }
            #pragma unroll
            for (int nt = 0; nt < 8; nt++) {
                uint4 bq = FragB[(nt * 4 + ks) * 33 + lane];
                mma16(acc[nt], ahi, bq.x, bq.y);
                mma16(acc[nt], ahi, bq.z, bq.w);
                mma16(acc[nt], alo, bq.x, bq.y);
            }
        }
    }

    // epilogue: split + scatter into g_Q / g_K / g_Vt (hi/lo)
    const int mA = m0 + 16 * w + r, mB = mA + 8;
    #pragma unroll
    for (int nt = 0; nt < 8; nt++) {
        const int d = dcol0 + nt * 8 + 2 * c;
        const int hh = d >> 6, dk = d & 63;
        #pragma unroll
        for (int hm = 0; hm < 2; hm++) {
            const int m = hm ? mB : mA;
            const int bb = m >> 11, ss = m & 2047;
            uint32_t hi, lo;
            split2(acc[nt][2 * hm], acc[nt][2 * hm + 1], hi, lo);
            if (part == 2) {
                half2 h2 = *reinterpret_cast<half2*>(&hi);
                half2 l2 = *reinterpret_cast<half2*>(&lo);
                const size_t vb = ((size_t)(bb * H + hh) * DK + dk) * S + ss;
                g_Vth[vb]     = __low2half(h2);
                g_Vth[vb + S] = __high2half(h2);
                g_Vtl[vb]     = __low2half(l2);
                g_Vtl[vb + S] = __high2half(l2);
            } else {
                const size_t qb = ((size_t)(bb * H + hh) * S + ss) * DK + dk;
                half* dsth = (part == 0) ? g_Qh : g_Kh;
                half* dstl = (part == 0) ? g_Ql : g_Kl;
                *(uint32_t*)(dsth + qb) = hi;
                *(uint32_t*)(dstl + qb) = lo;
            }
        }
    }
}

// ============================================================
// scores = Q@K^T*scale + mask, fused online softmax stats.
// 256 thr (8 warps), q-strip 128, k chunks 64. grid (16, 32)
// ============================================================
__global__ __launch_bounds__(256) void scores_mma_kernel(const float* __restrict__ mask)
{
    __shared__ __align__(16) char sraw[18432];         // Q stage / FragB union
    half*  Qst = (half*)sraw;                          // [128][72]
    uint4* FragB = (uint4*)sraw;                       // [8*4*33]
    uint32_t* Fw = (uint32_t*)sraw;

    const int t = threadIdx.x, w = t >> 5, lane = t & 31;
    const int r = lane >> 2, c = lane & 3;
    const int bh = blockIdx.y, q0 = blockIdx.x * 128;
    const half* Qhb = g_Qh + ((size_t)bh * S + q0) * DK;
    const half* Qlb = g_Ql + ((size_t)bh * S + q0) * DK;
    const half* Khb = g_Kh + (size_t)bh * S * DK;
    const half* Klb = g_Kl + (size_t)bh * S * DK;
    float* Sp = g_Sc + (size_t)bh * S * S;

    uint32_t Ahi[4][4], Alo[4][4];
    // stage Qh, extract hi frags; then Ql, extract lo frags
    // NOTE: q-strip is 128 rows x 64 k = 1024 uint4 -> 4 iterations of 256 thr.
    #pragma unroll
    for (int pass = 0; pass < 2; pass++) {
        const half* src = pass ? Qlb : Qhb;
        __syncthreads();
        #pragma unroll
        for (int i = 0; i < 4; i++) {
            int idx = t + i * 256;
            int row = idx >> 3, k8 = (idx & 7) << 3;
            *(uint4*)&Qst[row * 72 + k8] =
                *(const uint4*)(src + (size_t)row * 64 + k8);
        }
        __syncthreads();
        #pragma unroll
        for (int ks = 0; ks < 4; ks++)
            #pragma unroll
            for (int i = 0; i < 4; i++) {
                const int row = 16 * w + r + ((i & 1) << 3);
                const int col = ks * 16 + 2 * c + ((i >> 1) << 3);
                uint32_t v = *(const uint32_t*)&Qst[row * 72 + col];
                if (pass) Alo[ks][i] = v; else Ahi[ks][i] = v;
            }
    }

    const int qA = q0 + 16 * w + r, qB = qA + 8;
    float mA = -CUDART_INF_F, lA = 0.f, mB = -CUDART_INF_F, lB = 0.f;

    for (int kc = 0; kc < 32; kc++) {
        __syncthreads();
        #pragma unroll
        for (int i = 0; i < 2; i++) {
            int idx = t + i * 256;
            int n = idx >> 3, k8 = (idx & 7) << 3;
            const size_t ofs = (size_t)(kc * 64 + n) * 64 + k8;
            uint4 vh = *(const uint4*)(Khb + ofs);
            uint4 vl = *(const uint4*)(Klb + ofs);
            scat_b(Fw, n, k8, vh, 0);
            scat_b(Fw, n, k8, vl, 2);
        }
        __syncthreads();

        const int kt = kc * 64;
        #pragma unroll
        for (int nt = 0; nt < 8; nt++) {
            float d[4] = {};
            #pragma unroll
            for (int ks = 0; ks < 4; ks++) {
                uint4 bq = FragB[(nt * 4 + ks) * 33 + lane];
                mma16(d, Ahi[ks], bq.x, bq.y);
                mma16(d, Ahi[ks], bq.z, bq.w);
                mma16(d, Alo[ks], bq.x, bq.y);
            }
            const int col = kt + nt * 8 + 2 * c;
            const float2 mk0 = *(const float2*)(mask + (size_t)qA * S + col);
            const float2 mk1 = *(const float2*)(mask + (size_t)qB * S + col);
            const float v0 = fmaf(d[0], SCALE, mk0.x), v1 = fmaf(d[1], SCALE, mk0.y);
            const float v2 = fmaf(d[2], SCALE, mk1.x), v3 = fmaf(d[3], SCALE, mk1.y);
            float2 s01 = {v0, v1}, s23 = {v2, v3};
            *(float2*)(Sp + (size_t)qA * S + col) = s01;
            *(float2*)(Sp + (size_t)qB * S + col) = s23;
            onl(mA, lA, v0, v1);
            onl(mB, lB, v2, v3);
        }
    }

    merge_sh(mA, lA, 1); merge_sh(mA, lA, 2);
    merge_sh(mB, lB, 1); merge_sh(mB, lB, 2);
    if (c == 0) {
        g_M[bh * S + qA] = mA; g_Li[bh * S + qA] = 1.f / lA;
        g_M[bh * S + qB] = mB; g_Li[bh * S + qB] = 1.f / lB;
    }
}

// ============================================================
// ctx = softmax(S) @ V : P on the fly, V^T permuted B-frags.
// 256 thr, q-strip 128, k chunks 64. grid (16, 32)
// ============================================================
__global__ __launch_bounds__(256) void ctx_mma_kernel()
{
    __shared__ uint4 FragB[8 * 4 * 33];
    uint32_t* Fw = (uint32_t*)FragB;

    const int t = threadIdx.x, w = t >> 5, lane = t & 31;
    const int r = lane >> 2, c = lane & 3;
    const int bh = blockIdx.y, q0 = blockIdx.x * 128;
    const int b = bh >> 3, h = bh & 7;
    const float* Sp = g_Sc + (size_t)bh * S * S;
    const half* Vhb = g_Vth + (size_t)bh * DK * S;
    const half* Vlb = g_Vtl + (size_t)bh * DK * S;

    const int qA = q0 + 16 * w + r, qB = qA + 8;
    const float mAv = g_M[bh * S + qA], liA = g_Li[bh * S + qA];
    const float mBv = g_M[bh * S + qB], liB = g_Li[bh * S + qB];

    float acc[8][4] = {};

    for (int kc = 0; kc < 32; kc++) {
        __syncthreads();
        #pragma unroll
        for (int i = 0; i < 2; i++) {
            int idx = t + i * 256;
            int n = idx >> 3, k8 = (idx & 7) << 3;   // n = dk row, k = s
            const size_t ofs = (size_t)n * S + kc * 64 + k8;
            uint4 vh = *(const uint4*)(Vhb + ofs);
            uint4 vl = *(const uint4*)(Vlb + ofs);
            scat_b(Fw, n, k8, vh, 0);
            scat_b(Fw, n, k8, vl, 2);
        }
        __syncthreads();

        const int kt = kc * 64;
        #pragma unroll
        for (int ks = 0; ks < 4; ks++) {
            const int k0 = kt + ks * 16 + 2 * c;
            const float2 sA0 = *(const float2*)(Sp + (size_t)qA * S + k0);
            const float2 sB0 = *(const float2*)(Sp + (size_t)qB * S + k0);
            const float2 sA1 = *(const float2*)(Sp + (size_t)qA * S + k0 + 8);
            const float2 sB1 = *(const float2*)(Sp + (size_t)qB * S + k0 + 8);
            uint32_t Ph[4], Pl[4];
            split2(__expf(sA0.x - mAv) * liA, __expf(sA0.y - mAv) * liA, Ph[0], Pl[0]);
            split2(__expf(sB0.x - mBv) * liB, __expf(sB0.y - mBv) * liB, Ph[1], Pl[1]);
            split2(__expf(sA1.x - mAv) * liA, __expf(sA1.y - mAv) * liA, Ph[2], Pl[2]);
            split2(__expf(sB1.x - mBv) * liB, __expf(sB1.y - mBv) * liB, Ph[3], Pl[3]);
            #pragma unroll
            for (int nt = 0; nt < 8; nt++) {
                uint4 bq = FragB[(nt * 4 + ks) * 33 + lane];
                mma16(acc[nt], Ph, bq.x, bq.y);
                mma16(acc[nt], Ph, bq.z, bq.w);
                mma16(acc[nt], Pl, bq.x, bq.y);
            }
        }
    }

    // epilogue: split ctx into g_Ch / g_Cl
    #pragma unroll
    for (int nt = 0; nt < 8; nt++) {
        const int col = h * 64 + nt * 8 + 2 * c;
        #pragma unroll
        for (int hm = 0; hm < 2; hm++) {
            const int q = hm ? qB : qA;
            uint32_t hi, lo;
            split2(acc[nt][2 * hm], acc[nt][2 * hm + 1], hi, lo);
            const size_t ofs = ((size_t)b * S + q) * 512 + col;
            *(uint32_t*)(g_Ch + ofs) = hi;
            *(uint32_t*)(g_Cl + ofs) = lo;
        }
    }
}

// ============================================================
// attn.mean over heads, recomputing probs from raw scores.
// ============================================================
__global__ __launch_bounds__(256) void mean_kernel(float* __restrict__ mean)
{
    const size_t i4 = (size_t)blockIdx.x * 256 + threadIdx.x;   // < B*S*S/4
    const size_t per_b = (size_t)S * S / 4;
    const int bb = (int)(i4 / per_b);
    const size_t r4 = i4 - (size_t)bb * per_b;
    const int q  = (int)(r4 / (S / 4));
    const int k4 = (int)(r4 % (S / 4)) * 4;

    float4 acc = {0.f, 0.f, 0.f, 0.f};
    #pragma unroll
    for (int hh = 0; hh < H; hh++) {
        const int row = (bb * H + hh) * S + q;
        const float m  = __ldg(&g_M[row]);
        const float li = __ldg(&g_Li[row]);
        const float4 s = *(const float4*)(g_Sc + (size_t)row * S + k4);
        acc.x += __expf(s.x - m) * li;
        acc.y += __expf(s.y - m) * li;
        acc.z += __expf(s.z - m) * li;
        acc.w += __expf(s.w - m) * li;
    }
    acc.x *= 0.125f; acc.y *= 0.125f; acc.z *= 0.125f; acc.w *= 0.125f;
    ((float4*)mean)[i4] = acc;
}

// ============================================================
// out = Ctx @ Wout : pre-split A and B, permuted B-frags.
// 128 thr, m-strip 64, n-tile 64. grid (128, 8)
// ============================================================
__global__ __launch_bounds__(128) void out_mma_kernel(float* __restrict__ out)
{
    __shared__ __align__(16) half Ast[2][64 * 72];
    __shared__ uint4 FragB[8 * 4 * 33];
    uint32_t* Fw = (uint32_t*)FragB;

    const int t = threadIdx.x, w = t >> 5, lane = t & 31;
    const int r = lane >> 2, c = lane & 3;
    const int m0 = blockIdx.x * 64;
    const int n0 = blockIdx.y * 64;

    float acc[8][4] = {};

    for (int kt = 0; kt < 512; kt += 64) {
        __syncthreads();
        #pragma unroll
        for (int i = 0; i < 4; i++) {
            int idx = t + i * 128;
            int row = idx >> 3, k8 = (idx & 7) << 3;
            *(uint4*)&Ast[0][row * 72 + k8] =
                *(const uint4*)(g_Ch + (size_t)(m0 + row) * 512 + kt + k8);
            *(uint4*)&Ast[1][row * 72 + k8] =
                *(const uint4*)(g_Cl + (size_t)(m0 + row) * 512 + kt + k8);
        }
        #pragma unroll
        for (int i = 0; i < 4; i++) {
            int idx = t + i * 128;
            int n = idx >> 3, k8 = (idx & 7) << 3;
            uint4 vh = *(const uint4*)(g_WoTh + (size_t)(n0 + n) * 512 + kt + k8);
            uint4 vl = *(const uint4*)(g_WoTl + (size_t)(n0 + n) * 512 + kt + k8);
            scat_b(Fw, n, k8, vh, 0);
            scat_b(Fw, n, k8, vl, 2);
        }
        __syncthreads();

        #pragma unroll
        for (int ks = 0; ks < 4; ks++) {
            uint32_t ahi[4], alo[4];
            #pragma unroll
            for (int i = 0; i < 4; i++) {
                const int row = 16 * w + r + ((i & 1) << 3);
                const int col = ks * 16 + 2 * c + ((i >> 1) << 3);
                ahi[i] = *(const uint32_t*)&Ast[0][row * 72 + col];
                alo[i] = *(const uint32_t*)&Ast[1][row * 72 + col];
            }
            #pragma unroll
            for (int nt = 0; nt < 8; nt++) {
                uint4 bq = FragB[(nt * 4 + ks) * 33 + lane];
                mma16(acc[nt], ahi, bq.x, bq.y);
                mma16(acc[nt], ahi, bq.z, bq.w);
                mma16(acc[nt], alo, bq.x, bq.y);
            }
        }
    }

    const int mA = m0 + 16 * w + r, mB = mA + 8;
    #pragma unroll
    for (int nt = 0; nt < 8; nt++) {
        const int col = n0 + nt * 8 + 2 * c;
        float2 oA = {acc[nt][0], acc[nt][1]};
        float2 oB = {acc[nt][2], acc[nt][3]};
        *(float2*)(out + (size_t)mA * 512 + col) = oA;
        *(float2*)(out + (size_t)mB * 512 + col) = oB;
    }
}

// ============================================================
extern "C" void kernel_launch(void* const* d_in, const int* in_sizes, int n_in,
                              void* d_out, int out_size)
{
    const float* Zq   = (const float*)d_in[0];
    const float* Zkv  = (const float*)d_in[1];
    const float* mask = (const float*)d_in[2];
    const float* Wqkv = (const float*)d_in[3];
    const float* Wout = (const float*)d_in[4];

    float* out  = (float*)d_out;                 // [B,S,D]
    float* mean = out + (size_t)B * S * D;       // [B,S,S]

    // prep: split inputs
    half *zqh, *zql, *zkh, *zkl, *wqh, *wql, *woh, *wol;
    cudaGetSymbolAddress((void**)&zqh, g_Zqh);
    cudaGetSymbolAddress((void**)&zql, g_Zql);
    cudaGetSymbolAddress((void**)&zkh, g_Zkh);
    cudaGetSymbolAddress((void**)&zkl, g_Zkl);
    cudaGetSymbolAddress((void**)&wqh, g_WqTh);
    cudaGetSymbolAddress((void**)&wql, g_WqTl);
    cudaGetSymbolAddress((void**)&woh, g_WoTh);
    cudaGetSymbolAddress((void**)&wol, g_WoTl);

    const int nZ4 = B * S * D / 4;               // 1048576
    split_kernel<<<nZ4 / 256, 256>>>((const float4*)Zq,  (uint2*)zqh, (uint2*)zql, nZ4);
    split_kernel<<<nZ4 / 256, 256>>>((const float4*)Zkv, (uint2*)zkh, (uint2*)zkl, nZ4);
    tsplit_kernel<<<(D / 8 * 3 * D) / 256, 256>>>(Wqkv, wqh, wql, D, 3 * D);
    tsplit_kernel<<<(D / 8 * D) / 256, 256>>>(Wout, woh, wol, D, D);

    qkv_mma_kernel<<<dim3(128, 24), 128>>>();
    scores_mma_kernel<<<dim3(16, 32), 256>>>(mask);
    ctx_mma_kernel<<<dim3(16, 32), 256>>>();
    mean_kernel<<<(B * (size_t)S * S / 4) / 256, 256>>>(mean);
    out_mma_kernel<<<dim3(128, 8), 128>>>(out);
}